// round 12
// baseline (speedup 1.0000x reference)
#include <cuda_runtime.h>
#include <cuda_bf16.h>

// ---------------------------------------------------------------------------
// Attention_26379689132660 — fused single kernel, f32x2, latency-optimized.
//
// Algebraic collapse: the network is affine in the 3-channel z_t, folding to
// per-head 3x3 forms:
//   score_h(t) = vq_h . z_t,  vq_h = u_h + z7^T M_h   (SC*log2e folded in;
//     t-constant terms dropped: softmax-invariant; scores bounded -> no max)
//   out = pC + sum_h G_h zbar_h,  zbar_h = softmax-mean of z_t
//
// R10 changes (occ/overlap, not work):
//  * one-pass softmax: esum+zb accumulated in the score loop, sc[8] gone
//    (-16 regs).
//  * 128-thread blocks x 1024, __launch_bounds__(128,5): ~5 resident blocks
//    per SM whose load/fold/compute phases interleave -> DRAM and FMA overlap
//    instead of alternating at block-wide barriers.
// ---------------------------------------------------------------------------

typedef unsigned long long u64;

__device__ __forceinline__ u64 pk2(float x, float y) {
    u64 r; asm("mov.b64 %0,{%1,%2};" : "=l"(r) : "f"(x), "f"(y)); return r;
}
__device__ __forceinline__ void up2(u64 v, float& x, float& y) {
    asm("mov.b64 {%0,%1},%2;" : "=f"(x), "=f"(y) : "l"(v));
}
__device__ __forceinline__ u64 f2fma(u64 a, u64 b, u64 c) {
    u64 d; asm("fma.rn.f32x2 %0,%1,%2,%3;" : "=l"(d) : "l"(a), "l"(b), "l"(c)); return d;
}
__device__ __forceinline__ u64 f2mul(u64 a, u64 b) {
    u64 d; asm("mul.rn.f32x2 %0,%1,%2;" : "=l"(d) : "l"(a), "l"(b)); return d;
}
__device__ __forceinline__ u64 f2add(u64 a, u64 b) {
    u64 d; asm("add.rn.f32x2 %0,%1,%2;" : "=l"(d) : "l"(a), "l"(b)); return d;
}
__device__ __forceinline__ float ex2a(float x) {
    float y; asm("ex2.approx.ftz.f32 %0,%1;" : "=f"(y) : "f"(x)); return y;
}
__device__ __forceinline__ float rcpa(float x) {
    float y; asm("rcp.approx.ftz.f32 %0,%1;" : "=f"(y) : "f"(x)); return y;
}

// SC = (1/sqrt(8)) * log2(e), folded into M and u.
#define SC_FOLD (0.3535533905932738f * 1.4426950408889634f)

__global__ __launch_bounds__(128, 5) void attn_fused_kernel(
    const u64* __restrict__ Z2,      // (4,8,3,256,256) viewed as float2/u64
    u64* __restrict__ O2,            // (4,3,256,256)   viewed as float2/u64
    const float* __restrict__ W_in, const float* __restrict__ b_in,
    const float* __restrict__ W_q,  const float* __restrict__ b_q,
    const float* __restrict__ W_k,
    const float* __restrict__ W_v,  const float* __restrict__ b_v,
    const float* __restrict__ W_o,  const float* __restrict__ b_o)
{
    __shared__ float sW[3][1024];          // Wq, Wk, Wv (coalesced-staged)
    __shared__ float sWin[96], sWo[96];
    __shared__ float sbq[32], sbv[32], sbin[32];
    __shared__ float sA[3][96];            // A_X[d*3+c] = (W_X @ W_in)
    __shared__ float sCq[32], sCv[32];
    __shared__ u64 pM[4][9], pU[4][3], pG[4][9], pC[3];  // lane-duplicated

    const int tid    = threadIdx.x;
    const int plane2 = 32768;              // float2 per 256x256 plane
    const int b      = blockIdx.x >> 8;    // 256 blocks per batch
    const int g0     = (blockIdx.x & 255) * 128;

    // ---- Stage 0: issue this thread's 24 pixel-pair loads FIRST (LDG.64,
    // coalesced); latency hidden behind weight staging + fold below.
    u64 z2[8][3];
    {
        const u64* p = Z2 + (size_t)b * 24 * plane2 + g0 + tid;
        #pragma unroll
        for (int t = 0; t < 8; t++)
            #pragma unroll
            for (int c = 0; c < 3; c++)
                z2[t][c] = __ldg(p + (t * 3 + c) * plane2);
    }

    // ---- Stage 0b: stage weights into smem, coalesced.
    #pragma unroll
    for (int k = 0; k < 8; k++) {
        int i = k * 128 + tid;
        sW[0][i] = W_q[i]; sW[1][i] = W_k[i]; sW[2][i] = W_v[i];
    }
    if (tid < 96) { sWin[tid] = W_in[tid]; sWo[tid] = W_o[tid]; }
    if (tid < 32)       sbq[tid]       = b_q[tid];
    else if (tid < 64)  sbv[tid - 32]  = b_v[tid - 32];
    else if (tid < 96)  sbin[tid - 64] = b_in[tid - 64];
    __syncthreads();

    // ---- Stage 1: A_X = W_X @ W_in (288 vals), c_q / c_v (64 vals).
    #pragma unroll
    for (int k = 0; k < 3; k++) {
        int idx = k * 128 + tid;
        if (idx < 288) {
            int X = idx / 96, r = idx % 96, d = r / 3, c = r % 3;
            float s = 0.f;
            #pragma unroll
            for (int i = 0; i < 32; i++) s += sW[X][d * 32 + i] * sWin[i * 3 + c];
            sA[X][r] = s;
        }
    }
    if (tid >= 64 && tid < 128) {
        int q = tid - 64;
        int X = (q < 32) ? 0 : 2;          // q or v
        int d = q & 31;
        float s = (q < 32) ? sbq[d] : sbv[d];
        #pragma unroll
        for (int i = 0; i < 32; i++) s += sW[X][d * 32 + i] * sbin[i];
        if (q < 32) sCq[d] = s; else sCv[d] = s;
    }
    __syncthreads();

    // ---- Stage 2: 87 derived scalars, lane-duplicated u64.
    if (tid < 36) {                        // M[h][a][c] (fold SC)
        int h = tid / 9, a = (tid / 3) % 3, c = tid % 3;
        float s = 0.f;
        #pragma unroll
        for (int j = 0; j < 8; j++)
            s += sA[0][(h * 8 + j) * 3 + a] * sA[1][(h * 8 + j) * 3 + c];
        s *= SC_FOLD;
        pM[h][a * 3 + c] = pk2(s, s);
    } else if (tid < 48) {                 // u[h][c] (fold SC)
        int t2 = tid - 36, h = t2 / 3, c = t2 % 3;
        float s = 0.f;
        #pragma unroll
        for (int j = 0; j < 8; j++) s += sCq[h * 8 + j] * sA[1][(h * 8 + j) * 3 + c];
        s *= SC_FOLD;
        pU[h][c] = pk2(s, s);
    } else if (tid < 84) {                 // G[h][o][c]
        int t2 = tid - 48, h = t2 / 9, o = (t2 / 3) % 3, c = t2 % 3;
        float s = 0.f;
        #pragma unroll
        for (int j = 0; j < 8; j++) s += sWo[o * 32 + h * 8 + j] * sA[2][(h * 8 + j) * 3 + c];
        pG[h][o * 3 + c] = pk2(s, s);
    } else if (tid < 87) {                 // pC[o] = b_o + W_o . c_v
        int o = tid - 84;
        float s = b_o[o];
        #pragma unroll
        for (int d = 0; d < 32; d++) s += sWo[o * 32 + d] * sCv[d];
        pC[o] = pk2(s, s);
    }
    __syncthreads();

    // ---- Stage 3: attention, 2 pixels/thread in f32x2 lanes.
    // One-pass softmax: esum and zb accumulated inside the score loop.
    u64 o0 = pC[0], o1 = pC[1], o2 = pC[2];

    #pragma unroll
    for (int hd = 0; hd < 4; hd++) {
        u64 vq0 = f2fma(z2[7][0], pM[hd][0], pU[hd][0]);
        vq0     = f2fma(z2[7][1], pM[hd][3], vq0);
        vq0     = f2fma(z2[7][2], pM[hd][6], vq0);
        u64 vq1 = f2fma(z2[7][0], pM[hd][1], pU[hd][1]);
        vq1     = f2fma(z2[7][1], pM[hd][4], vq1);
        vq1     = f2fma(z2[7][2], pM[hd][7], vq1);
        u64 vq2 = f2fma(z2[7][0], pM[hd][2], pU[hd][2]);
        vq2     = f2fma(z2[7][1], pM[hd][5], vq2);
        vq2     = f2fma(z2[7][2], pM[hd][8], vq2);

        u64 esum = 0, zb0 = 0, zb1 = 0, zb2 = 0;
        #pragma unroll
        for (int t = 0; t < 8; t++) {
            u64 s = f2mul(vq0, z2[t][0]);
            s = f2fma(vq1, z2[t][1], s);
            s = f2fma(vq2, z2[t][2], s);
            float a, c; up2(s, a, c);
            u64 e = pk2(ex2a(a), ex2a(c));
            esum = f2add(esum, e);
            zb0 = f2fma(e, z2[t][0], zb0);
            zb1 = f2fma(e, z2[t][1], zb1);
            zb2 = f2fma(e, z2[t][2], zb2);
        }
        float e0, e1; up2(esum, e0, e1);
        u64 pinv = pk2(rcpa(e0), rcpa(e1));

        zb0 = f2mul(zb0, pinv); zb1 = f2mul(zb1, pinv); zb2 = f2mul(zb2, pinv);

        o0 = f2fma(pG[hd][0], zb0, o0);
        o0 = f2fma(pG[hd][1], zb1, o0);
        o0 = f2fma(pG[hd][2], zb2, o0);
        o1 = f2fma(pG[hd][3], zb0, o1);
        o1 = f2fma(pG[hd][4], zb1, o1);
        o1 = f2fma(pG[hd][5], zb2, o1);
        o2 = f2fma(pG[hd][6], zb0, o2);
        o2 = f2fma(pG[hd][7], zb1, o2);
        o2 = f2fma(pG[hd][8], zb2, o2);
    }

    // ---- Stage 4: coalesced STG.64, 3 planes.
    u64* op = O2 + (size_t)b * 3 * plane2 + g0 + tid;
    op[0]          = o0;
    op[plane2]     = o1;
    op[2 * plane2] = o2;
}

extern "C" void kernel_launch(void* const* d_in, const int* in_sizes, int n_in,
                              void* d_out, int out_size)
{
    const float* Z    = (const float*)d_in[0];
    const float* W_in = (const float*)d_in[1];
    const float* b_in = (const float*)d_in[2];
    const float* W_q  = (const float*)d_in[3];
    const float* b_q  = (const float*)d_in[4];
    const float* W_k  = (const float*)d_in[5];
    // b_k (d_in[6]) provably unused: its score contribution is constant over t
    const float* W_v  = (const float*)d_in[7];
    const float* b_v  = (const float*)d_in[8];
    const float* W_o  = (const float*)d_in[9];
    const float* b_o  = (const float*)d_in[10];

    // 262144 pixels / 2 per thread / 128 threads = 1024 blocks, one kernel.
    attn_fused_kernel<<<1024, 128>>>(
        (const u64*)Z, (u64*)d_out,
        W_in, b_in, W_q, b_q, W_k, W_v, b_v, W_o, b_o);
}

// round 13
// speedup vs baseline: 1.1189x; 1.1189x over previous
#include <cuda_runtime.h>
#include <cuda_bf16.h>

// ---------------------------------------------------------------------------
// Attention_26379689132660 — fused kernel, LDG.128 loads + f32x2 math.
//
// Algebraic collapse: the network is affine in the 3-channel z_t, folding to
// per-head 3x3 forms:
//   score_h(t) = vq_h . z_t,  vq_h = u_h + z7^T M_h   (SC*log2e folded in;
//     t-constant terms dropped: softmax-invariant; scores bounded -> no max)
//   out = pC + sum_h G_h zbar_h,  zbar_h = softmax-mean of z_t
//
// R12 lesson: with occupancy pinned at ~12-17 warps/SM by the z-register
// footprint, DRAM throughput tracks per-thread bytes-in-flight. R4 (LDG.128)
// beat both LDG.64 variants. So: 4 pixels/thread via ulonglong2 (16B loads,
// 24 per thread) + two independent f32x2 lanes-pair chains for the math.
// Fold stays fused in-kernel (coalesced weight staging), z loads issued first.
// ---------------------------------------------------------------------------

typedef unsigned long long u64;

__device__ __forceinline__ u64 pk2(float x, float y) {
    u64 r; asm("mov.b64 %0,{%1,%2};" : "=l"(r) : "f"(x), "f"(y)); return r;
}
__device__ __forceinline__ void up2(u64 v, float& x, float& y) {
    asm("mov.b64 {%0,%1},%2;" : "=f"(x), "=f"(y) : "l"(v));
}
__device__ __forceinline__ u64 f2fma(u64 a, u64 b, u64 c) {
    u64 d; asm("fma.rn.f32x2 %0,%1,%2,%3;" : "=l"(d) : "l"(a), "l"(b), "l"(c)); return d;
}
__device__ __forceinline__ u64 f2mul(u64 a, u64 b) {
    u64 d; asm("mul.rn.f32x2 %0,%1,%2;" : "=l"(d) : "l"(a), "l"(b)); return d;
}
__device__ __forceinline__ u64 f2add(u64 a, u64 b) {
    u64 d; asm("add.rn.f32x2 %0,%1,%2;" : "=l"(d) : "l"(a), "l"(b)); return d;
}
__device__ __forceinline__ float ex2a(float x) {
    float y; asm("ex2.approx.ftz.f32 %0,%1;" : "=f"(y) : "f"(x)); return y;
}
__device__ __forceinline__ float rcpa(float x) {
    float y; asm("rcp.approx.ftz.f32 %0,%1;" : "=f"(y) : "f"(x)); return y;
}

// SC = (1/sqrt(8)) * log2(e), folded into M and u.
#define SC_FOLD (0.3535533905932738f * 1.4426950408889634f)

__global__ __launch_bounds__(128, 3) void attn_fused_kernel(
    const ulonglong2* __restrict__ Z4,   // (4,8,3,256,256): 4 px per load
    ulonglong2* __restrict__ O4,         // (4,3,256,256):   4 px per store
    const float* __restrict__ W_in, const float* __restrict__ b_in,
    const float* __restrict__ W_q,  const float* __restrict__ b_q,
    const float* __restrict__ W_k,
    const float* __restrict__ W_v,  const float* __restrict__ b_v,
    const float* __restrict__ W_o,  const float* __restrict__ b_o)
{
    __shared__ float sW[3][1024];          // Wq, Wk, Wv (coalesced-staged)
    __shared__ float sWin[96], sWo[96];
    __shared__ float sbq[32], sbv[32], sbin[32];
    __shared__ float sA[3][96];            // A_X[d*3+c] = (W_X @ W_in)
    __shared__ float sCq[32], sCv[32];
    __shared__ u64 pM[4][9], pU[4][3], pG[4][9], pC[3];  // lane-duplicated

    const int tid    = threadIdx.x;
    const int plane4 = 16384;              // ulonglong2 per 256x256 plane
    const int b      = blockIdx.x >> 7;    // 128 blocks per batch
    const int g0     = (blockIdx.x & 127) * 128;

    // ---- Stage 0: issue 24 LDG.128 FIRST (4 px x 8 tokens x 3 channels).
    // Latency hidden behind weight staging + fold below.
    // z[0] = pixel pair (0,1), z[1] = pixel pair (2,3), each lane-packed f32x2.
    u64 z[2][8][3];
    {
        const ulonglong2* p = Z4 + (size_t)b * 24 * plane4 + g0 + tid;
        #pragma unroll
        for (int t = 0; t < 8; t++)
            #pragma unroll
            for (int c = 0; c < 3; c++) {
                ulonglong2 v = __ldg(p + (t * 3 + c) * plane4);
                z[0][t][c] = v.x;
                z[1][t][c] = v.y;
            }
    }

    // ---- Stage 0b: stage weights into smem, coalesced.
    #pragma unroll
    for (int k = 0; k < 8; k++) {
        int i = k * 128 + tid;
        sW[0][i] = W_q[i]; sW[1][i] = W_k[i]; sW[2][i] = W_v[i];
    }
    if (tid < 96) { sWin[tid] = W_in[tid]; sWo[tid] = W_o[tid]; }
    if (tid < 32)       sbq[tid]       = b_q[tid];
    else if (tid < 64)  sbv[tid - 32]  = b_v[tid - 32];
    else if (tid < 96)  sbin[tid - 64] = b_in[tid - 64];
    __syncthreads();

    // ---- Stage 1: A_X = W_X @ W_in (288 vals), c_q / c_v (64 vals).
    #pragma unroll
    for (int k = 0; k < 3; k++) {
        int idx = k * 128 + tid;
        if (idx < 288) {
            int X = idx / 96, r = idx % 96, d = r / 3, c = r % 3;
            float s = 0.f;
            #pragma unroll
            for (int i = 0; i < 32; i++) s += sW[X][d * 32 + i] * sWin[i * 3 + c];
            sA[X][r] = s;
        }
    }
    if (tid >= 64 && tid < 128) {
        int q = tid - 64;
        int X = (q < 32) ? 0 : 2;          // q or v
        int d = q & 31;
        float s = (q < 32) ? sbq[d] : sbv[d];
        #pragma unroll
        for (int i = 0; i < 32; i++) s += sW[X][d * 32 + i] * sbin[i];
        if (q < 32) sCq[d] = s; else sCv[d] = s;
    }
    __syncthreads();

    // ---- Stage 2: 87 derived scalars, lane-duplicated u64.
    if (tid < 36) {                        // M[h][a][c] (fold SC)
        int h = tid / 9, a = (tid / 3) % 3, c = tid % 3;
        float s = 0.f;
        #pragma unroll
        for (int j = 0; j < 8; j++)
            s += sA[0][(h * 8 + j) * 3 + a] * sA[1][(h * 8 + j) * 3 + c];
        s *= SC_FOLD;
        pM[h][a * 3 + c] = pk2(s, s);
    } else if (tid < 48) {                 // u[h][c] (fold SC)
        int t2 = tid - 36, h = t2 / 3, c = t2 % 3;
        float s = 0.f;
        #pragma unroll
        for (int j = 0; j < 8; j++) s += sCq[h * 8 + j] * sA[1][(h * 8 + j) * 3 + c];
        s *= SC_FOLD;
        pU[h][c] = pk2(s, s);
    } else if (tid < 84) {                 // G[h][o][c]
        int t2 = tid - 48, h = t2 / 9, o = (t2 / 3) % 3, c = t2 % 3;
        float s = 0.f;
        #pragma unroll
        for (int j = 0; j < 8; j++) s += sWo[o * 32 + h * 8 + j] * sA[2][(h * 8 + j) * 3 + c];
        pG[h][o * 3 + c] = pk2(s, s);
    } else if (tid < 87) {                 // pC[o] = b_o + W_o . c_v
        int o = tid - 84;
        float s = b_o[o];
        #pragma unroll
        for (int d = 0; d < 32; d++) s += sWo[o * 32 + d] * sCv[d];
        pC[o] = pk2(s, s);
    }
    __syncthreads();

    // ---- Stage 3: attention math — two independent f32x2 chains (pixel
    // pairs), interleaved for ILP. One-pass softmax.
    u64 o[2][3];
    o[0][0] = pC[0]; o[0][1] = pC[1]; o[0][2] = pC[2];
    o[1][0] = pC[0]; o[1][1] = pC[1]; o[1][2] = pC[2];

    #pragma unroll
    for (int hd = 0; hd < 4; hd++) {
        #pragma unroll
        for (int p = 0; p < 2; p++) {
            u64 vq0 = f2fma(z[p][7][0], pM[hd][0], pU[hd][0]);
            vq0     = f2fma(z[p][7][1], pM[hd][3], vq0);
            vq0     = f2fma(z[p][7][2], pM[hd][6], vq0);
            u64 vq1 = f2fma(z[p][7][0], pM[hd][1], pU[hd][1]);
            vq1     = f2fma(z[p][7][1], pM[hd][4], vq1);
            vq1     = f2fma(z[p][7][2], pM[hd][7], vq1);
            u64 vq2 = f2fma(z[p][7][0], pM[hd][2], pU[hd][2]);
            vq2     = f2fma(z[p][7][1], pM[hd][5], vq2);
            vq2     = f2fma(z[p][7][2], pM[hd][8], vq2);

            u64 esum = 0, zb0 = 0, zb1 = 0, zb2 = 0;
            #pragma unroll
            for (int t = 0; t < 8; t++) {
                u64 s = f2mul(vq0, z[p][t][0]);
                s = f2fma(vq1, z[p][t][1], s);
                s = f2fma(vq2, z[p][t][2], s);
                float a, c; up2(s, a, c);
                u64 e = pk2(ex2a(a), ex2a(c));
                esum = f2add(esum, e);
                zb0 = f2fma(e, z[p][t][0], zb0);
                zb1 = f2fma(e, z[p][t][1], zb1);
                zb2 = f2fma(e, z[p][t][2], zb2);
            }
            float e0, e1; up2(esum, e0, e1);
            u64 pinv = pk2(rcpa(e0), rcpa(e1));

            zb0 = f2mul(zb0, pinv); zb1 = f2mul(zb1, pinv); zb2 = f2mul(zb2, pinv);

            o[p][0] = f2fma(pG[hd][0], zb0, o[p][0]);
            o[p][0] = f2fma(pG[hd][1], zb1, o[p][0]);
            o[p][0] = f2fma(pG[hd][2], zb2, o[p][0]);
            o[p][1] = f2fma(pG[hd][3], zb0, o[p][1]);
            o[p][1] = f2fma(pG[hd][4], zb1, o[p][1]);
            o[p][1] = f2fma(pG[hd][5], zb2, o[p][1]);
            o[p][2] = f2fma(pG[hd][6], zb0, o[p][2]);
            o[p][2] = f2fma(pG[hd][7], zb1, o[p][2]);
            o[p][2] = f2fma(pG[hd][8], zb2, o[p][2]);
        }
    }

    // ---- Stage 4: coalesced STG.128 (4 px per store), 3 planes.
    ulonglong2* op = O4 + (size_t)b * 3 * plane4 + g0 + tid;
    ulonglong2 r0; r0.x = o[0][0]; r0.y = o[1][0];
    ulonglong2 r1; r1.x = o[0][1]; r1.y = o[1][1];
    ulonglong2 r2; r2.x = o[0][2]; r2.y = o[1][2];
    op[0]          = r0;
    op[plane4]     = r1;
    op[2 * plane4] = r2;
}

extern "C" void kernel_launch(void* const* d_in, const int* in_sizes, int n_in,
                              void* d_out, int out_size)
{
    const float* Z    = (const float*)d_in[0];
    const float* W_in = (const float*)d_in[1];
    const float* b_in = (const float*)d_in[2];
    const float* W_q  = (const float*)d_in[3];
    const float* b_q  = (const float*)d_in[4];
    const float* W_k  = (const float*)d_in[5];
    // b_k (d_in[6]) provably unused: its score contribution is constant over t
    const float* W_v  = (const float*)d_in[7];
    const float* b_v  = (const float*)d_in[8];
    const float* W_o  = (const float*)d_in[9];
    const float* b_o  = (const float*)d_in[10];

    // 262144 pixels / 4 per thread / 128 threads = 512 blocks, one kernel.
    attn_fused_kernel<<<512, 128>>>(
        (const ulonglong2*)Z, (ulonglong2*)d_out,
        W_in, b_in, W_q, b_q, W_k, W_v, b_v, W_o, b_o);
}